// round 1
// baseline (speedup 1.0000x reference)
#include <cuda_runtime.h>
#include <cuda_bf16.h>
#include <math.h>

// ---------------- problem constants ----------------
#define BB 4
#define LL 512
#define VV 32000
#define DD 1024
#define HH 16
#define HD 64
#define NLAYER 2
#define EE 8
#define KK 2
#define FF 4096
#define SS (BB*LL)      // 2048
#define CAP 320
#define D3 (3*DD)       // 3072

// ---------------- static scratch ----------------
__device__ float g_x[SS*DD];
__device__ float g_qkv[SS*D3];
__device__ float g_q[SS*DD];
__device__ float g_k[SS*DD];
__device__ float g_v[SS*DD];
__device__ float g_av[SS*DD];
__device__ float g_sc[BB*HH*LL*LL];     // 64 MB
__device__ float g_attn[SS*DD];
__device__ float g_tmp[SS*DD];
__device__ float g_xe[EE*CAP*DD];
__device__ float g_hbuf[EE*CAP*FF];
__device__ float g_oe[EE*CAP*DD];
__device__ int   g_topi[SS*2];
__device__ float g_topw[SS*2];
__device__ int   g_slot[EE*CAP];
__device__ float g_slotw[EE*CAP];

// ---------------- reductions ----------------
__device__ __forceinline__ float blockReduceSum(float v){
    __shared__ float sh[32];
    int lane = threadIdx.x & 31, wid = threadIdx.x >> 5;
    int nw = (blockDim.x + 31) >> 5;
    #pragma unroll
    for (int o = 16; o > 0; o >>= 1) v += __shfl_down_sync(0xffffffffu, v, o);
    __syncthreads();                  // protect sh reuse across calls
    if (lane == 0) sh[wid] = v;
    __syncthreads();
    if (wid == 0) {
        v = (lane < nw) ? sh[lane] : 0.f;
        #pragma unroll
        for (int o = 16; o > 0; o >>= 1) v += __shfl_down_sync(0xffffffffu, v, o);
        if (lane == 0) sh[0] = v;
    }
    __syncthreads();
    return sh[0];
}

__device__ __forceinline__ float blockReduceMax(float v){
    __shared__ float sh[32];
    int lane = threadIdx.x & 31, wid = threadIdx.x >> 5;
    int nw = (blockDim.x + 31) >> 5;
    #pragma unroll
    for (int o = 16; o > 0; o >>= 1) v = fmaxf(v, __shfl_down_sync(0xffffffffu, v, o));
    __syncthreads();
    if (lane == 0) sh[wid] = v;
    __syncthreads();
    if (wid == 0) {
        v = (lane < nw) ? sh[lane] : -1e30f;
        #pragma unroll
        for (int o = 16; o > 0; o >>= 1) v = fmaxf(v, __shfl_down_sync(0xffffffffu, v, o));
        if (lane == 0) sh[0] = v;
    }
    __syncthreads();
    return sh[0];
}

// ---------------- GEMM: C = act(alpha * A(MxK) * B(NxK)^T + bias) ----------------
// batched via grid.z with explicit element strides
#define BM 64
#define BN 64
#define BKT 16

__global__ void gemm_bt(const float* __restrict__ A, const float* __restrict__ Bm,
                        const float* __restrict__ bias, float* __restrict__ C,
                        int M, int N, int K, int lda, int ldb, int ldc,
                        long aStride, long bStride, long cStride, long biasStride,
                        float alpha, int relu)
{
    int z = blockIdx.z;
    A  += (long)z * aStride;
    Bm += (long)z * bStride;
    C  += (long)z * cStride;
    if (bias) bias += (long)z * biasStride;

    __shared__ float As[BKT][BM];
    __shared__ float Bs[BKT][BN];
    int tx = threadIdx.x, ty = threadIdx.y;
    int tid = ty * 16 + tx;
    int m0 = blockIdx.y * BM, n0 = blockIdx.x * BN;
    int lk = tid & 15;    // k within tile
    int lr = tid >> 4;    // row group

    float acc[4][4] = {};
    for (int kt = 0; kt < K; kt += BKT) {
        #pragma unroll
        for (int i = 0; i < 4; i++) {
            int row = lr + i * 16;
            int gk = kt + lk;
            int gm = m0 + row;
            int gn = n0 + row;
            As[lk][row] = (gm < M && gk < K) ? A[(long)gm * lda + gk] : 0.f;
            Bs[lk][row] = (gn < N && gk < K) ? Bm[(long)gn * ldb + gk] : 0.f;
        }
        __syncthreads();
        #pragma unroll
        for (int k = 0; k < BKT; k++) {
            float a[4], b[4];
            #pragma unroll
            for (int i = 0; i < 4; i++) a[i] = As[k][ty * 4 + i];
            #pragma unroll
            for (int j = 0; j < 4; j++) b[j] = Bs[k][tx * 4 + j];
            #pragma unroll
            for (int i = 0; i < 4; i++)
                #pragma unroll
                for (int j = 0; j < 4; j++)
                    acc[i][j] += a[i] * b[j];
        }
        __syncthreads();
    }
    #pragma unroll
    for (int i = 0; i < 4; i++) {
        int gm = m0 + ty * 4 + i;
        if (gm >= M) continue;
        #pragma unroll
        for (int j = 0; j < 4; j++) {
            int gn = n0 + tx * 4 + j;
            if (gn >= N) continue;
            float v = acc[i][j] * alpha;
            if (bias) v += bias[gn];
            if (relu) v = fmaxf(v, 0.f);
            C[(long)gm * ldc + gn] = v;
        }
    }
}

// ---------------- GEMM: C = A(MxK) * B(KxN), both row-major ----------------
__global__ void gemm_nn(const float* __restrict__ A, const float* __restrict__ Bm,
                        float* __restrict__ C,
                        int M, int N, int K, int lda, int ldb, int ldc,
                        long aStride, long bStride, long cStride)
{
    int z = blockIdx.z;
    A  += (long)z * aStride;
    Bm += (long)z * bStride;
    C  += (long)z * cStride;

    __shared__ float As[BKT][BM];
    __shared__ float Bs[BKT][BN];
    int tx = threadIdx.x, ty = threadIdx.y;
    int tid = ty * 16 + tx;
    int m0 = blockIdx.y * BM, n0 = blockIdx.x * BN;
    int lk = tid & 15;
    int lr = tid >> 4;
    int bcol = tid & 63;     // 0..63
    int bkr  = tid >> 6;     // 0..3

    float acc[4][4] = {};
    for (int kt = 0; kt < K; kt += BKT) {
        #pragma unroll
        for (int i = 0; i < 4; i++) {
            int row = lr + i * 16;
            int gk = kt + lk;
            int gm = m0 + row;
            As[lk][row] = (gm < M && gk < K) ? A[(long)gm * lda + gk] : 0.f;
        }
        #pragma unroll
        for (int i = 0; i < 4; i++) {
            int k = bkr + i * 4;
            int gk = kt + k;
            int gn = n0 + bcol;
            Bs[k][bcol] = (gk < K && gn < N) ? Bm[(long)gk * ldb + gn] : 0.f;
        }
        __syncthreads();
        #pragma unroll
        for (int k = 0; k < BKT; k++) {
            float a[4], b[4];
            #pragma unroll
            for (int i = 0; i < 4; i++) a[i] = As[k][ty * 4 + i];
            #pragma unroll
            for (int j = 0; j < 4; j++) b[j] = Bs[k][tx * 4 + j];
            #pragma unroll
            for (int i = 0; i < 4; i++)
                #pragma unroll
                for (int j = 0; j < 4; j++)
                    acc[i][j] += a[i] * b[j];
        }
        __syncthreads();
    }
    #pragma unroll
    for (int i = 0; i < 4; i++) {
        int gm = m0 + ty * 4 + i;
        if (gm >= M) continue;
        #pragma unroll
        for (int j = 0; j < 4; j++) {
            int gn = n0 + tx * 4 + j;
            if (gn >= N) continue;
            C[(long)gm * ldc + gn] = acc[i][j];
        }
    }
}

// ---------------- embedding + positional encoding ----------------
__global__ void embed_kernel(const int* __restrict__ src, const float* __restrict__ emb,
                             float* __restrict__ x)
{
    long i = (long)blockIdx.x * 256 + threadIdx.x;   // over SS*DD
    int s = (int)(i >> 10);
    int d = (int)(i & 1023);
    int l = s & (LL - 1);
    int tok = src[s];
    int half2 = (d >> 1) * 2;
    float div = __expf(-(float)half2 * (logf(10000.f) / (float)DD));
    float arg = (float)l * div;
    float pe = (d & 1) ? cosf(arg) : sinf(arg);
    x[i] = emb[(long)tok * DD + d] * 32.0f + pe;
}

// ---------------- head split / merge ----------------
__global__ void split_heads(const float* __restrict__ qkv,
                            float* __restrict__ q, float* __restrict__ k, float* __restrict__ v)
{
    long i = (long)blockIdx.x * 256 + threadIdx.x;   // over SS*DD
    int s = (int)(i >> 10);
    int dc = (int)(i & 1023);
    int h = dc >> 6;
    int d = dc & 63;
    int b = s >> 9;          // /512
    int l = s & 511;
    long srcoff = (long)s * D3 + h * HD + d;
    long dst = (((long)(b * HH + h) * LL) + l) * HD + d;
    q[dst] = qkv[srcoff];
    k[dst] = qkv[srcoff + DD];
    v[dst] = qkv[srcoff + 2 * DD];
}

__global__ void merge_heads(const float* __restrict__ av, float* __restrict__ out)
{
    long i = (long)blockIdx.x * 256 + threadIdx.x;   // over SS*DD
    int s = (int)(i >> 10);
    int dc = (int)(i & 1023);
    int h = dc >> 6;
    int d = dc & 63;
    int b = s >> 9;
    int l = s & 511;
    long srcoff = (((long)(b * HH + h) * LL) + l) * HD + d;
    out[i] = av[srcoff];
}

// ---------------- causal softmax (in place) ----------------
__global__ void softmax_causal(float* __restrict__ sc)
{
    int row = blockIdx.x;              // z*LL + q
    int q = row & (LL - 1);
    float* s = sc + (long)row * LL;
    int t = threadIdx.x;               // 128 threads

    float mx = -1e30f;
    for (int k = t; k <= q; k += 128) mx = fmaxf(mx, s[k]);
    mx = blockReduceMax(mx);

    float sum = 0.f;
    for (int k = t; k <= q; k += 128) {
        float e = expf(s[k] - mx);
        s[k] = e;
        sum += e;
    }
    sum = blockReduceSum(sum);
    float inv = 1.f / sum;
    for (int k = t; k <= q; k += 128) s[k] *= inv;
    for (int k = q + 1 + t; k < LL; k += 128) s[k] = 0.f;
}

// ---------------- residual + layernorm ----------------
__global__ void add_ln(const float* __restrict__ a, const float* __restrict__ b,
                       const float* __restrict__ w, const float* __restrict__ bb,
                       float* __restrict__ out)
{
    int row = blockIdx.x;
    int t = threadIdx.x;   // 256 threads
    const float* pa = a + (long)row * DD;
    const float* pb = b + (long)row * DD;
    float v[4];
    float s = 0.f;
    #pragma unroll
    for (int i = 0; i < 4; i++) {
        int d = t + i * 256;
        v[i] = pa[d] + pb[d];
        s += v[i];
    }
    s = blockReduceSum(s);
    float mean = s * (1.f / DD);
    float qq = 0.f;
    #pragma unroll
    for (int i = 0; i < 4; i++) {
        float dd = v[i] - mean;
        qq += dd * dd;
    }
    qq = blockReduceSum(qq);
    float inv = rsqrtf(qq * (1.f / DD) + 1e-5f);
    #pragma unroll
    for (int i = 0; i < 4; i++) {
        int d = t + i * 256;
        out[(long)row * DD + d] = (v[i] - mean) * inv * w[d] + bb[d];
    }
}

// ---------------- MoE gating: logits -> softmax -> top2 (normalized) ----------------
__global__ void gate_topk(const float* __restrict__ x, const float* __restrict__ gw,
                          const float* __restrict__ gb,
                          int* __restrict__ topi, float* __restrict__ topw)
{
    __shared__ float sh[EE * 256];
    int s = blockIdx.x, t = threadIdx.x;
    float p[EE];
    #pragma unroll
    for (int e = 0; e < EE; e++) p[e] = 0.f;
    for (int d = t; d < DD; d += 256) {
        float xv = x[(long)s * DD + d];
        #pragma unroll
        for (int e = 0; e < EE; e++) p[e] += xv * gw[e * DD + d];
    }
    #pragma unroll
    for (int e = 0; e < EE; e++) sh[e * 256 + t] = p[e];
    __syncthreads();
    for (int o = 128; o > 0; o >>= 1) {
        if (t < o) {
            #pragma unroll
            for (int e = 0; e < EE; e++) sh[e * 256 + t] += sh[e * 256 + t + o];
        }
        __syncthreads();
    }
    if (t == 0) {
        float lg[EE];
        float mx = -1e30f;
        #pragma unroll
        for (int e = 0; e < EE; e++) { lg[e] = sh[e * 256] + gb[e]; mx = fmaxf(mx, lg[e]); }
        float sum = 0.f;
        #pragma unroll
        for (int e = 0; e < EE; e++) { lg[e] = expf(lg[e] - mx); sum += lg[e]; }
        float invs = 1.f / sum;
        #pragma unroll
        for (int e = 0; e < EE; e++) lg[e] *= invs;
        int i0 = 0;
        #pragma unroll
        for (int e = 1; e < EE; e++) if (lg[e] > lg[i0]) i0 = e;
        int i1 = (i0 == 0) ? 1 : 0;
        #pragma unroll
        for (int e = 0; e < EE; e++) if (e != i0 && lg[e] > lg[i1]) i1 = e;
        float w0 = lg[i0], w1 = lg[i1];
        float ws = 1.f / (w0 + w1);
        topi[2 * s]     = i0;
        topi[2 * s + 1] = i1;
        topw[2 * s]     = w0 * ws;
        topw[2 * s + 1] = w1 * ws;
    }
}

// ---------------- deterministic capacity routing (token order preserved) ----------------
__global__ void route_kernel(const int* __restrict__ topi, const float* __restrict__ topw,
                             int* __restrict__ slot, float* __restrict__ slotw)
{
    int e = blockIdx.x;
    if (threadIdx.x != 0) return;
    int cnt = 0;
    for (int s = 0; s < SS && cnt < CAP; s++) {
        float w = -1.f;
        if (topi[2 * s] == e) w = topw[2 * s];
        else if (topi[2 * s + 1] == e) w = topw[2 * s + 1];
        if (w >= 0.f) {
            slot[e * CAP + cnt] = s;
            slotw[e * CAP + cnt] = w;
            cnt++;
        }
    }
    for (; cnt < CAP; cnt++) {
        slot[e * CAP + cnt] = -1;
        slotw[e * CAP + cnt] = 0.f;
    }
}

__global__ void gather_xe(const float* __restrict__ x, const int* __restrict__ slot,
                          float* __restrict__ xe)
{
    int sl = blockIdx.x;   // E*CAP
    int t = slot[sl];
    float* dst = xe + (long)sl * DD;
    if (t < 0) {
        for (int d = threadIdx.x; d < DD; d += 256) dst[d] = 0.f;
    } else {
        const float* srcp = x + (long)t * DD;
        for (int d = threadIdx.x; d < DD; d += 256) dst[d] = srcp[d];
    }
}

__global__ void scatter_oe(const float* __restrict__ oe, const int* __restrict__ slot,
                           const float* __restrict__ slotw, float* __restrict__ y)
{
    int sl = blockIdx.x;
    int t = slot[sl];
    if (t < 0) return;
    float w = slotw[sl];
    const float* srcp = oe + (long)sl * DD;
    float* dst = y + (long)t * DD;
    for (int d = threadIdx.x; d < DD; d += 256) atomicAdd(&dst[d], srcp[d] * w);
}

// ---------------- host launcher ----------------
extern "C" void kernel_launch(void* const* d_in, const int* in_sizes, int n_in,
                              void* d_out, int out_size)
{
    const int*   src        = (const int*)  d_in[0];
    const float* emb        = (const float*)d_in[1];
    const float* in_proj_w  = (const float*)d_in[2];
    const float* in_proj_b  = (const float*)d_in[3];
    const float* out_proj_w = (const float*)d_in[4];
    const float* out_proj_b = (const float*)d_in[5];
    const float* ln1_w      = (const float*)d_in[6];
    const float* ln1_b      = (const float*)d_in[7];
    const float* ln2_w      = (const float*)d_in[8];
    const float* ln2_b      = (const float*)d_in[9];
    const float* gate_w     = (const float*)d_in[10];
    const float* gate_b     = (const float*)d_in[11];
    const float* w1         = (const float*)d_in[12];
    const float* b1         = (const float*)d_in[13];
    const float* w2         = (const float*)d_in[14];
    const float* b2         = (const float*)d_in[15];
    const float* dec_w      = (const float*)d_in[16];
    const float* dec_b      = (const float*)d_in[17];
    float* out = (float*)d_out;

    float *x, *qkv, *q, *k, *v, *av, *sc, *attn, *tmp, *xe, *hbuf, *oe, *topw, *slotw;
    int *topi, *slot;
    cudaGetSymbolAddress((void**)&x,    g_x);
    cudaGetSymbolAddress((void**)&qkv,  g_qkv);
    cudaGetSymbolAddress((void**)&q,    g_q);
    cudaGetSymbolAddress((void**)&k,    g_k);
    cudaGetSymbolAddress((void**)&v,    g_v);
    cudaGetSymbolAddress((void**)&av,   g_av);
    cudaGetSymbolAddress((void**)&sc,   g_sc);
    cudaGetSymbolAddress((void**)&attn, g_attn);
    cudaGetSymbolAddress((void**)&tmp,  g_tmp);
    cudaGetSymbolAddress((void**)&xe,   g_xe);
    cudaGetSymbolAddress((void**)&hbuf, g_hbuf);
    cudaGetSymbolAddress((void**)&oe,   g_oe);
    cudaGetSymbolAddress((void**)&topi, g_topi);
    cudaGetSymbolAddress((void**)&topw, g_topw);
    cudaGetSymbolAddress((void**)&slot, g_slot);
    cudaGetSymbolAddress((void**)&slotw, g_slotw);

    dim3 blk(16, 16);

    embed_kernel<<<(SS * DD) / 256, 256>>>(src, emb, x);

    for (int l = 0; l < NLAYER; l++) {
        const float* wi = in_proj_w  + (long)l * D3 * DD;
        const float* bi = in_proj_b  + (long)l * D3;
        const float* wo = out_proj_w + (long)l * DD * DD;
        const float* bo = out_proj_b + (long)l * DD;
        const float* gw = gate_w     + (long)l * EE * DD;
        const float* gb = gate_b     + (long)l * EE;
        const float* w1l = w1        + (long)l * EE * FF * DD;
        const float* b1l = b1        + (long)l * EE * FF;
        const float* w2l = w2        + (long)l * EE * DD * FF;
        const float* b2l = b2        + (long)l * EE * DD;

        // qkv = x @ wi^T + bi   [2048 x 3072]
        gemm_bt<<<dim3(D3 / 64, SS / 64, 1), blk>>>(x, wi, bi, qkv,
            SS, D3, DD, DD, DD, D3, 0, 0, 0, 0, 1.f, 0);

        split_heads<<<(SS * DD) / 256, 256>>>(qkv, q, k, v);

        // scores = q @ k^T / 8   batch = B*H = 64
        gemm_bt<<<dim3(LL / 64, LL / 64, BB * HH), blk>>>(q, k, nullptr, sc,
            LL, LL, HD, HD, HD, LL,
            (long)LL * HD, (long)LL * HD, (long)LL * LL, 0, 0.125f, 0);

        softmax_causal<<<BB * HH * LL, 128>>>(sc);

        // av = attn @ v   [512 x 64] per (b,h)
        gemm_nn<<<dim3(1, LL / 64, BB * HH), blk>>>(sc, v, av,
            LL, HD, LL, LL, HD, HD,
            (long)LL * LL, (long)LL * HD, (long)LL * HD);

        merge_heads<<<(SS * DD) / 256, 256>>>(av, attn);

        // proj = attn @ wo^T + bo
        gemm_bt<<<dim3(DD / 64, SS / 64, 1), blk>>>(attn, wo, bo, tmp,
            SS, DD, DD, DD, DD, DD, 0, 0, 0, 0, 1.f, 0);

        add_ln<<<SS, 256>>>(x, tmp, ln1_w + l * DD, ln1_b + l * DD, x);

        // ---- MoE ----
        gate_topk<<<SS, 256>>>(x, gw, gb, topi, topw);
        route_kernel<<<EE, 32>>>(topi, topw, slot, slotw);
        gather_xe<<<EE * CAP, 256>>>(x, slot, xe);

        // h = relu(xe @ w1^T + b1)   batch = 8, [320 x 4096]
        gemm_bt<<<dim3(FF / 64, CAP / 64, EE), blk>>>(xe, w1l, b1l, hbuf,
            CAP, FF, DD, DD, DD, FF,
            (long)CAP * DD, (long)FF * DD, (long)CAP * FF, FF, 1.f, 1);

        // oe = h @ w2^T + b2   batch = 8, [320 x 1024]
        gemm_bt<<<dim3(DD / 64, CAP / 64, EE), blk>>>(hbuf, w2l, b2l, oe,
            CAP, DD, FF, FF, FF, DD,
            (long)CAP * FF, (long)DD * FF, (long)CAP * DD, DD, 1.f, 0);

        cudaMemsetAsync(tmp, 0, (size_t)SS * DD * sizeof(float), 0);
        scatter_oe<<<EE * CAP, 256>>>(oe, slot, slotw, tmp);

        add_ln<<<SS, 256>>>(x, tmp, ln2_w + l * DD, ln2_b + l * DD, x);
    }

    // logits = x @ dec_w^T + dec_b   [2048 x 32000]
    gemm_bt<<<dim3(VV / 64, SS / 64, 1), blk>>>(x, dec_w, dec_b, out,
        SS, VV, DD, DD, DD, VV, 0, 0, 0, 0, 1.f, 0);
}

// round 2
// speedup vs baseline: 2.3697x; 2.3697x over previous
#include <cuda_runtime.h>
#include <cuda_bf16.h>
#include <math.h>

// ---------------- problem constants ----------------
#define BB 4
#define LL 512
#define VV 32000
#define DD 1024
#define HH 16
#define HD 64
#define NLAYER 2
#define EE 8
#define KK 2
#define FF 4096
#define SS (BB*LL)      // 2048
#define CAP 320
#define D3 (3*DD)       // 3072

// ---------------- static scratch ----------------
__device__ float g_x[SS*DD];
__device__ float g_qkv[SS*D3];
__device__ float g_q[SS*DD];
__device__ float g_k[SS*DD];
__device__ float g_vt[SS*DD];           // V stored transposed per head: [(b,h), d, l]
__device__ float g_av[SS*DD];
__device__ float g_sc[BB*HH*LL*LL];     // 64 MB
__device__ float g_attn[SS*DD];
__device__ float g_tmp[SS*DD];
__device__ float g_xe[EE*CAP*DD];
__device__ float g_hbuf[EE*CAP*FF];
__device__ float g_oe[EE*CAP*DD];
__device__ int   g_topi[SS*2];
__device__ float g_topw[SS*2];
__device__ int   g_slot[EE*CAP];
__device__ float g_slotw[EE*CAP];

// ---------------- reductions ----------------
__device__ __forceinline__ float blockReduceSum(float v){
    __shared__ float sh[32];
    int lane = threadIdx.x & 31, wid = threadIdx.x >> 5;
    int nw = (blockDim.x + 31) >> 5;
    #pragma unroll
    for (int o = 16; o > 0; o >>= 1) v += __shfl_down_sync(0xffffffffu, v, o);
    __syncthreads();
    if (lane == 0) sh[wid] = v;
    __syncthreads();
    if (wid == 0) {
        v = (lane < nw) ? sh[lane] : 0.f;
        #pragma unroll
        for (int o = 16; o > 0; o >>= 1) v += __shfl_down_sync(0xffffffffu, v, o);
        if (lane == 0) sh[0] = v;
    }
    __syncthreads();
    return sh[0];
}

__device__ __forceinline__ float blockReduceMax(float v){
    __shared__ float sh[32];
    int lane = threadIdx.x & 31, wid = threadIdx.x >> 5;
    int nw = (blockDim.x + 31) >> 5;
    #pragma unroll
    for (int o = 16; o > 0; o >>= 1) v = fmaxf(v, __shfl_down_sync(0xffffffffu, v, o));
    __syncthreads();
    if (lane == 0) sh[wid] = v;
    __syncthreads();
    if (wid == 0) {
        v = (lane < nw) ? sh[lane] : -1e30f;
        #pragma unroll
        for (int o = 16; o > 0; o >>= 1) v = fmaxf(v, __shfl_down_sync(0xffffffffu, v, o));
        if (lane == 0) sh[0] = v;
    }
    __syncthreads();
    return sh[0];
}

// ============================================================
// Tensor-core GEMM (tf32, 2-term error-compensated split):
//   C = act(alpha * A(MxK) * B(NxK)^T + bias)
// Block tile 128x128x32, 8 warps, warp tile 64x32, mma m16n8k8.
// A,B split into (hi, lo) tf32 parts; D += Ah*Bh + Ah*Bl + Al*Bh
// gives ~fp32 accuracy on the tensor pipe.
// ============================================================
#define GBM 128
#define GBN 128
#define GBK 32
#define GPAD 36   // stride pad: (4n+k) covers all 32 banks

#define MMA_TF32(d, a, b) \
    asm volatile("mma.sync.aligned.m16n8k8.row.col.f32.tf32.tf32.f32 " \
        "{%0,%1,%2,%3},{%4,%5,%6,%7},{%8,%9},{%0,%1,%2,%3};" \
        : "+f"(d[0]), "+f"(d[1]), "+f"(d[2]), "+f"(d[3]) \
        : "r"(a[0]), "r"(a[1]), "r"(a[2]), "r"(a[3]), "r"(b[0]), "r"(b[1]))

__device__ __forceinline__ void split_tf32(float v, float& hi, float& lo){
    unsigned h, l;
    asm("cvt.rna.tf32.f32 %0, %1;" : "=r"(h) : "f"(v));
    float hf = __uint_as_float(h);
    asm("cvt.rna.tf32.f32 %0, %1;" : "=r"(l) : "f"(v - hf));
    hi = hf; lo = __uint_as_float(l);
}

__global__ void gemm_tc(const float* __restrict__ A, const float* __restrict__ Bm,
                        const float* __restrict__ bias, float* __restrict__ C,
                        int M, int N, int K, int lda, int ldb, int ldc,
                        long aStride, long bStride, long cStride, long biasStride,
                        float alpha, int relu)
{
    extern __shared__ float smbuf[];
    float* Ah = smbuf;
    float* Al = Ah + GBM * GPAD;
    float* Bh = Al + GBM * GPAD;
    float* Bl = Bh + GBN * GPAD;

    int z = blockIdx.z;
    A  += (long)z * aStride;
    Bm += (long)z * bStride;
    C  += (long)z * cStride;
    if (bias) bias += (long)z * biasStride;

    int m0 = blockIdx.x * GBM;
    int n0 = blockIdx.y * GBN;
    int tid = threadIdx.x;
    int wid = tid >> 5, lane = tid & 31;
    int wm = (wid & 1) * 64;        // warp m-origin within block
    int wn = (wid >> 1) * 32;       // warp n-origin within block

    float c[4][4][4];
    #pragma unroll
    for (int i = 0; i < 4; i++)
        #pragma unroll
        for (int j = 0; j < 4; j++)
            #pragma unroll
            for (int r = 0; r < 4; r++) c[i][j][r] = 0.f;

    int lrow = tid >> 3;           // 0..31
    int lcol = (tid & 7) * 4;      // 0..28

    for (int kt = 0; kt < K; kt += GBK) {
        // ---- load A tile (128x32) ----
        #pragma unroll
        for (int r = 0; r < 4; r++) {
            int row = lrow + r * 32;
            int gm = m0 + row;
            float4 v = make_float4(0.f, 0.f, 0.f, 0.f);
            if (gm < M) v = *(const float4*)(A + (long)gm * lda + kt + lcol);
            float h0,l0,h1,l1,h2,l2,h3,l3;
            split_tf32(v.x, h0, l0); split_tf32(v.y, h1, l1);
            split_tf32(v.z, h2, l2); split_tf32(v.w, h3, l3);
            float* ph = Ah + row * GPAD + lcol;
            float* pl = Al + row * GPAD + lcol;
            ph[0]=h0; ph[1]=h1; ph[2]=h2; ph[3]=h3;
            pl[0]=l0; pl[1]=l1; pl[2]=l2; pl[3]=l3;
        }
        // ---- load B tile (128x32), rows are N ----
        #pragma unroll
        for (int r = 0; r < 4; r++) {
            int row = lrow + r * 32;
            int gn = n0 + row;
            float4 v = make_float4(0.f, 0.f, 0.f, 0.f);
            if (gn < N) v = *(const float4*)(Bm + (long)gn * ldb + kt + lcol);
            float h0,l0,h1,l1,h2,l2,h3,l3;
            split_tf32(v.x, h0, l0); split_tf32(v.y, h1, l1);
            split_tf32(v.z, h2, l2); split_tf32(v.w, h3, l3);
            float* ph = Bh + row * GPAD + lcol;
            float* pl = Bl + row * GPAD + lcol;
            ph[0]=h0; ph[1]=h1; ph[2]=h2; ph[3]=h3;
            pl[0]=l0; pl[1]=l1; pl[2]=l2; pl[3]=l3;
        }
        __syncthreads();

        #pragma unroll
        for (int ks = 0; ks < GBK / 8; ks++) {
            int kk = ks * 8;
            unsigned ah[4][4], al[4][4], bh[4][2], bl[4][2];
            int ar = lane >> 2, ac = kk + (lane & 3);
            #pragma unroll
            for (int i = 0; i < 4; i++) {
                int r0 = wm + i * 16 + ar;
                ah[i][0] = __float_as_uint(Ah[r0 * GPAD + ac]);
                ah[i][1] = __float_as_uint(Ah[(r0 + 8) * GPAD + ac]);
                ah[i][2] = __float_as_uint(Ah[r0 * GPAD + ac + 4]);
                ah[i][3] = __float_as_uint(Ah[(r0 + 8) * GPAD + ac + 4]);
                al[i][0] = __float_as_uint(Al[r0 * GPAD + ac]);
                al[i][1] = __float_as_uint(Al[(r0 + 8) * GPAD + ac]);
                al[i][2] = __float_as_uint(Al[r0 * GPAD + ac + 4]);
                al[i][3] = __float_as_uint(Al[(r0 + 8) * GPAD + ac + 4]);
            }
            int bn = lane >> 2, bk = kk + (lane & 3);
            #pragma unroll
            for (int j = 0; j < 4; j++) {
                int nr = wn + j * 8 + bn;
                bh[j][0] = __float_as_uint(Bh[nr * GPAD + bk]);
                bh[j][1] = __float_as_uint(Bh[nr * GPAD + bk + 4]);
                bl[j][0] = __float_as_uint(Bl[nr * GPAD + bk]);
                bl[j][1] = __float_as_uint(Bl[nr * GPAD + bk + 4]);
            }
            #pragma unroll
            for (int i = 0; i < 4; i++)
                #pragma unroll
                for (int j = 0; j < 4; j++) {
                    MMA_TF32(c[i][j], ah[i], bh[j]);
                    MMA_TF32(c[i][j], ah[i], bl[j]);
                    MMA_TF32(c[i][j], al[i], bh[j]);
                }
        }
        __syncthreads();
    }

    // ---- epilogue ----
    int cr = lane >> 2, cc = (lane & 3) * 2;
    #pragma unroll
    for (int i = 0; i < 4; i++) {
        #pragma unroll
        for (int j = 0; j < 4; j++) {
            int gn = n0 + wn + j * 8 + cc;
            #pragma unroll
            for (int half = 0; half < 2; half++) {
                int gm = m0 + wm + i * 16 + cr + half * 8;
                if (gm >= M) continue;
                float v0 = c[i][j][half * 2 + 0] * alpha;
                float v1 = c[i][j][half * 2 + 1] * alpha;
                if (bias) {
                    if (gn < N)     v0 += bias[gn];
                    if (gn + 1 < N) v1 += bias[gn + 1];
                }
                if (relu) { v0 = fmaxf(v0, 0.f); v1 = fmaxf(v1, 0.f); }
                if (gn + 1 < N) {
                    *(float2*)(C + (long)gm * ldc + gn) = make_float2(v0, v1);
                } else if (gn < N) {
                    C[(long)gm * ldc + gn] = v0;
                }
            }
        }
    }
}

// ---------------- embedding + positional encoding ----------------
__global__ void embed_kernel(const int* __restrict__ src, const float* __restrict__ emb,
                             float* __restrict__ x)
{
    long i = (long)blockIdx.x * 256 + threadIdx.x;
    int s = (int)(i >> 10);
    int d = (int)(i & 1023);
    int l = s & (LL - 1);
    int tok = src[s];
    int half2 = (d >> 1) * 2;
    float div = __expf(-(float)half2 * (logf(10000.f) / (float)DD));
    float arg = (float)l * div;
    float pe = (d & 1) ? cosf(arg) : sinf(arg);
    x[i] = emb[(long)tok * DD + d] * 32.0f + pe;
}

// ---------------- head split (V transposed) / merge ----------------
__global__ void split_heads(const float* __restrict__ qkv,
                            float* __restrict__ q, float* __restrict__ k, float* __restrict__ vt)
{
    long i = (long)blockIdx.x * 256 + threadIdx.x;
    int s = (int)(i >> 10);
    int dc = (int)(i & 1023);
    int h = dc >> 6;
    int d = dc & 63;
    int b = s >> 9;
    int l = s & 511;
    long srcoff = (long)s * D3 + h * HD + d;
    long dst = (((long)(b * HH + h) * LL) + l) * HD + d;
    q[dst] = qkv[srcoff];
    k[dst] = qkv[srcoff + DD];
    long vdst = (((long)(b * HH + h) * HD) + d) * LL + l;
    vt[vdst] = qkv[srcoff + 2 * DD];
}

__global__ void merge_heads(const float* __restrict__ av, float* __restrict__ out)
{
    long i = (long)blockIdx.x * 256 + threadIdx.x;
    int s = (int)(i >> 10);
    int dc = (int)(i & 1023);
    int h = dc >> 6;
    int d = dc & 63;
    int b = s >> 9;
    int l = s & 511;
    long srcoff = (((long)(b * HH + h) * LL) + l) * HD + d;
    out[i] = av[srcoff];
}

// ---------------- causal softmax (in place) ----------------
__global__ void softmax_causal(float* __restrict__ sc)
{
    int row = blockIdx.x;
    int q = row & (LL - 1);
    float* s = sc + (long)row * LL;
    int t = threadIdx.x;

    float mx = -1e30f;
    for (int k = t; k <= q; k += 128) mx = fmaxf(mx, s[k]);
    mx = blockReduceMax(mx);

    float sum = 0.f;
    for (int k = t; k <= q; k += 128) {
        float e = expf(s[k] - mx);
        s[k] = e;
        sum += e;
    }
    sum = blockReduceSum(sum);
    float inv = 1.f / sum;
    for (int k = t; k <= q; k += 128) s[k] *= inv;
    for (int k = q + 1 + t; k < LL; k += 128) s[k] = 0.f;
}

// ---------------- residual + layernorm ----------------
__global__ void add_ln(const float* __restrict__ a, const float* __restrict__ b,
                       const float* __restrict__ w, const float* __restrict__ bb,
                       float* __restrict__ out)
{
    int row = blockIdx.x;
    int t = threadIdx.x;
    const float* pa = a + (long)row * DD;
    const float* pb = b + (long)row * DD;
    float v[4];
    float s = 0.f;
    #pragma unroll
    for (int i = 0; i < 4; i++) {
        int d = t + i * 256;
        v[i] = pa[d] + pb[d];
        s += v[i];
    }
    s = blockReduceSum(s);
    float mean = s * (1.f / DD);
    float qq = 0.f;
    #pragma unroll
    for (int i = 0; i < 4; i++) {
        float dd = v[i] - mean;
        qq += dd * dd;
    }
    qq = blockReduceSum(qq);
    float inv = rsqrtf(qq * (1.f / DD) + 1e-5f);
    #pragma unroll
    for (int i = 0; i < 4; i++) {
        int d = t + i * 256;
        out[(long)row * DD + d] = (v[i] - mean) * inv * w[d] + bb[d];
    }
}

// ---------------- MoE gating: logits -> softmax -> top2 (normalized) ----------------
__global__ void gate_topk(const float* __restrict__ x, const float* __restrict__ gw,
                          const float* __restrict__ gb,
                          int* __restrict__ topi, float* __restrict__ topw)
{
    __shared__ float sh[EE * 256];
    int s = blockIdx.x, t = threadIdx.x;
    float p[EE];
    #pragma unroll
    for (int e = 0; e < EE; e++) p[e] = 0.f;
    for (int d = t; d < DD; d += 256) {
        float xv = x[(long)s * DD + d];
        #pragma unroll
        for (int e = 0; e < EE; e++) p[e] += xv * gw[e * DD + d];
    }
    #pragma unroll
    for (int e = 0; e < EE; e++) sh[e * 256 + t] = p[e];
    __syncthreads();
    for (int o = 128; o > 0; o >>= 1) {
        if (t < o) {
            #pragma unroll
            for (int e = 0; e < EE; e++) sh[e * 256 + t] += sh[e * 256 + t + o];
        }
        __syncthreads();
    }
    if (t == 0) {
        float lg[EE];
        float mx = -1e30f;
        #pragma unroll
        for (int e = 0; e < EE; e++) { lg[e] = sh[e * 256] + gb[e]; mx = fmaxf(mx, lg[e]); }
        float sum = 0.f;
        #pragma unroll
        for (int e = 0; e < EE; e++) { lg[e] = expf(lg[e] - mx); sum += lg[e]; }
        float invs = 1.f / sum;
        #pragma unroll
        for (int e = 0; e < EE; e++) lg[e] *= invs;
        int i0 = 0;
        #pragma unroll
        for (int e = 1; e < EE; e++) if (lg[e] > lg[i0]) i0 = e;
        int i1 = (i0 == 0) ? 1 : 0;
        #pragma unroll
        for (int e = 0; e < EE; e++) if (e != i0 && lg[e] > lg[i1]) i1 = e;
        float w0 = lg[i0], w1 = lg[i1];
        float ws = 1.f / (w0 + w1);
        topi[2 * s]     = i0;
        topi[2 * s + 1] = i1;
        topw[2 * s]     = w0 * ws;
        topw[2 * s + 1] = w1 * ws;
    }
}

// ---------------- capacity routing: parallel block scan per expert ----------------
__global__ void route_kernel(const int* __restrict__ topi, const float* __restrict__ topw,
                             int* __restrict__ slot, float* __restrict__ slotw)
{
    __shared__ int cnt[256];
    int e = blockIdx.x;
    int t = threadIdx.x;           // 256 threads, 8 tokens each
    int base = t * 8;
    int loc[8]; float lw[8]; int c = 0;
    #pragma unroll
    for (int i = 0; i < 8; i++) {
        int s = base + i;
        float w = -1.f;
        if (topi[2 * s] == e) w = topw[2 * s];
        else if (topi[2 * s + 1] == e) w = topw[2 * s + 1];
        if (w >= 0.f) { loc[c] = s; lw[c] = w; c++; }
    }
    cnt[t] = c;
    __syncthreads();
    for (int off = 1; off < 256; off <<= 1) {
        int v = 0;
        if (t >= off) v = cnt[t - off];
        __syncthreads();
        cnt[t] += v;
        __syncthreads();
    }
    int start = cnt[t] - c;
    for (int i = 0; i < c; i++) {
        int pos = start + i;
        if (pos < CAP) {
            slot[e * CAP + pos]  = loc[i];
            slotw[e * CAP + pos] = lw[i];
        }
    }
    int total = cnt[255];
    __syncthreads();
    for (int p = total + t; p < CAP; p += 256) {
        slot[e * CAP + p]  = -1;
        slotw[e * CAP + p] = 0.f;
    }
}

__global__ void gather_xe(const float* __restrict__ x, const int* __restrict__ slot,
                          float* __restrict__ xe)
{
    int sl = blockIdx.x;
    int t = slot[sl];
    float* dst = xe + (long)sl * DD;
    if (t < 0) {
        for (int d = threadIdx.x; d < DD; d += 256) dst[d] = 0.f;
    } else {
        const float* srcp = x + (long)t * DD;
        for (int d = threadIdx.x; d < DD; d += 256) dst[d] = srcp[d];
    }
}

__global__ void scatter_oe(const float* __restrict__ oe, const int* __restrict__ slot,
                           const float* __restrict__ slotw, float* __restrict__ y)
{
    int sl = blockIdx.x;
    int t = slot[sl];
    if (t < 0) return;
    float w = slotw[sl];
    const float* srcp = oe + (long)sl * DD;
    float* dst = y + (long)t * DD;
    for (int d = threadIdx.x; d < DD; d += 256) atomicAdd(&dst[d], srcp[d] * w);
}

// ---------------- host launcher ----------------
static const int GEMM_SMEM = 4 * GBM * GPAD * (int)sizeof(float);  // 73728 B

extern "C" void kernel_launch(void* const* d_in, const int* in_sizes, int n_in,
                              void* d_out, int out_size)
{
    const int*   src        = (const int*)  d_in[0];
    const float* emb        = (const float*)d_in[1];
    const float* in_proj_w  = (const float*)d_in[2];
    const float* in_proj_b  = (const float*)d_in[3];
    const float* out_proj_w = (const float*)d_in[4];
    const float* out_proj_b = (const float*)d_in[5];
    const float* ln1_w      = (const float*)d_in[6];
    const float* ln1_b      = (const float*)d_in[7];
    const float* ln2_w      = (const float*)d_in[8];
    const float* ln2_b      = (const float*)d_in[9];
    const float* gate_w     = (const float*)d_in[10];
    const float* gate_b     = (const float*)d_in[11];
    const float* w1         = (const float*)d_in[12];
    const float* b1         = (const float*)d_in[13];
    const float* w2         = (const float*)d_in[14];
    const float* b2         = (const float*)d_in[15];
    const float* dec_w      = (const float*)d_in[16];
    const float* dec_b      = (const float*)d_in[17];
    float* out = (float*)d_out;

    static int smem_set = 0;
    if (!smem_set) {
        cudaFuncSetAttribute(gemm_tc, cudaFuncAttributeMaxDynamicSharedMemorySize, GEMM_SMEM);
        smem_set = 1;
    }

    float *x, *qkv, *q, *k, *vt, *av, *sc, *attn, *tmp, *xe, *hbuf, *oe, *topw, *slotw;
    int *topi, *slot;
    cudaGetSymbolAddress((void**)&x,    g_x);
    cudaGetSymbolAddress((void**)&qkv,  g_qkv);
    cudaGetSymbolAddress((void**)&q,    g_q);
    cudaGetSymbolAddress((void**)&k,    g_k);
    cudaGetSymbolAddress((void**)&vt,   g_vt);
    cudaGetSymbolAddress((void**)&av,   g_av);
    cudaGetSymbolAddress((void**)&sc,   g_sc);
    cudaGetSymbolAddress((void**)&attn, g_attn);
    cudaGetSymbolAddress((void**)&tmp,  g_tmp);
    cudaGetSymbolAddress((void**)&xe,   g_xe);
    cudaGetSymbolAddress((void**)&hbuf, g_hbuf);
    cudaGetSymbolAddress((void**)&oe,   g_oe);
    cudaGetSymbolAddress((void**)&topi, g_topi);
    cudaGetSymbolAddress((void**)&topw, g_topw);
    cudaGetSymbolAddress((void**)&slot, g_slot);
    cudaGetSymbolAddress((void**)&slotw, g_slotw);

    embed_kernel<<<(SS * DD) / 256, 256>>>(src, emb, x);

    for (int l = 0; l < NLAYER; l++) {
        const float* wi = in_proj_w  + (long)l * D3 * DD;
        const float* bi = in_proj_b  + (long)l * D3;
        const float* wo = out_proj_w + (long)l * DD * DD;
        const float* bo = out_proj_b + (long)l * DD;
        const float* gw = gate_w     + (long)l * EE * DD;
        const float* gb = gate_b     + (long)l * EE;
        const float* w1l = w1        + (long)l * EE * FF * DD;
        const float* b1l = b1        + (long)l * EE * FF;
        const float* w2l = w2        + (long)l * EE * DD * FF;
        const float* b2l = b2        + (long)l * EE * DD;

        // qkv = x @ wi^T + bi   [2048 x 3072], K=1024
        gemm_tc<<<dim3(SS/GBM, D3/GBN, 1), 256, GEMM_SMEM>>>(x, wi, bi, qkv,
            SS, D3, DD, DD, DD, D3, 0, 0, 0, 0, 1.f, 0);

        split_heads<<<(SS * DD) / 256, 256>>>(qkv, q, k, vt);

        // scores = q @ k^T / 8   batch = 64, M=N=512, K=64
        gemm_tc<<<dim3(LL/GBM, LL/GBN, BB*HH), 256, GEMM_SMEM>>>(q, k, nullptr, sc,
            LL, LL, HD, HD, HD, LL,
            (long)LL*HD, (long)LL*HD, (long)LL*LL, 0, 0.125f, 0);

        softmax_causal<<<BB * HH * LL, 128>>>(sc);

        // av = attn @ V = attn @ vt^T   batch=64, M=512, N=64, K=512
        gemm_tc<<<dim3(LL/GBM, 1, BB*HH), 256, GEMM_SMEM>>>(sc, vt, nullptr, av,
            LL, HD, LL, LL, LL, HD,
            (long)LL*LL, (long)HD*LL, (long)LL*HD, 0, 1.f, 0);

        merge_heads<<<(SS * DD) / 256, 256>>>(av, attn);

        // proj = attn @ wo^T + bo   [2048 x 1024], K=1024
        gemm_tc<<<dim3(SS/GBM, DD/GBN, 1), 256, GEMM_SMEM>>>(attn, wo, bo, tmp,
            SS, DD, DD, DD, DD, DD, 0, 0, 0, 0, 1.f, 0);

        add_ln<<<SS, 256>>>(x, tmp, ln1_w + l * DD, ln1_b + l * DD, x);

        // ---- MoE ----
        gate_topk<<<SS, 256>>>(x, gw, gb, topi, topw);
        route_kernel<<<EE, 256>>>(topi, topw, slot, slotw);
        gather_xe<<<EE * CAP, 256>>>(x, slot, xe);

        // h = relu(xe @ w1^T + b1)   batch=8, M=320, N=4096, K=1024
        gemm_tc<<<dim3((CAP+GBM-1)/GBM, FF/GBN, EE), 256, GEMM_SMEM>>>(xe, w1l, b1l, hbuf,
            CAP, FF, DD, DD, DD, FF,
            (long)CAP*DD, (long)FF*DD, (long)CAP*FF, FF, 1.f, 1);

        // oe = h @ w2^T + b2   batch=8, M=320, N=1024, K=4096
        gemm_tc<<<dim3((CAP+GBM-1)/GBM, DD/GBN, EE), 256, GEMM_SMEM>>>(hbuf, w2l, b2l, oe,
            CAP, DD, FF, FF, FF, DD,
            (long)CAP*FF, (long)DD*FF, (long)CAP*DD, DD, 1.f, 0);

        cudaMemsetAsync(tmp, 0, (size_t)SS * DD * sizeof(float), 0);
        scatter_oe<<<EE * CAP, 256>>>(oe, slot, slotw, tmp);

        add_ln<<<SS, 256>>>(x, tmp, ln2_w + l * DD, ln2_b + l * DD, x);
    }

    // logits = x @ dec_w^T + dec_b   [2048 x 32000], K=1024
    gemm_tc<<<dim3(SS/GBM, (VV+GBN-1)/GBN, 1), 256, GEMM_SMEM>>>(x, dec_w, dec_b, out,
        SS, VV, DD, DD, DD, VV, 0, 0, 0, 0, 1.f, 0);
}